// round 13
// baseline (speedup 1.0000x reference)
#include <cuda_runtime.h>
#include <cuda_fp16.h>
#include <cstdint>

// DynamicConvolution: B=16, Cin=Cout=128, K=3, H=W=64, pad=1, fp32.
// R12: no input pre-pass. Conv stages raw fp32 NCHW input (with h-halo, zfill)
// in smem once per cin-chunk (aligned cp.async), builds per-tap fp16 B tiles
// smem->smem (shift handled by LDS, no alignment constraint). Weights still
// repacked to [b][rs][cout][cin] fp16 by a fast 1024-block kernel.
// Conv geometry = R8: 512 thr, 128 cout x 256 spatial, 16 warps (64x32), K=32.

#define BB 16
#define CI 128
#define CO 128
#define HW 4096

__device__ __half g_wt[(size_t)BB * 9 * CO * CI];  // [b][rs][cout][cin] fp16

__device__ __forceinline__ uint32_t smem_u32(const void* p) {
    uint32_t a; asm("{ .reg .u64 t; cvta.to.shared.u64 t, %1; cvt.u32.u64 %0, t; }" : "=r"(a) : "l"(p));
    return a;
}
__device__ __forceinline__ void ldm_x4(uint32_t* r, uint32_t addr) {
    asm volatile("ldmatrix.sync.aligned.m8n8.x4.shared.b16 {%0,%1,%2,%3}, [%4];"
                 : "=r"(r[0]), "=r"(r[1]), "=r"(r[2]), "=r"(r[3]) : "r"(addr));
}

// ---- weight repack: [b][cout][cin][rs] -> [b][rs][cout][cin] fp16, 1024 blocks ----
__global__ __launch_bounds__(256) void prep_w(const float* __restrict__ w) {
    __shared__ float tw[2 * 1152];
    const int cp = blockIdx.x, b = blockIdx.y;          // cout pair
    const float* src = w + ((size_t)(b * CO + cp * 2)) * 1152;
#pragma unroll
    for (int i = 0; i < 9; ++i) tw[threadIdx.x + i * 256] = src[threadIdx.x + i * 256];
    __syncthreads();
    const int cl = threadIdx.x >> 7, cin = threadIdx.x & 127;
#pragma unroll
    for (int tap = 0; tap < 9; ++tap)
        g_wt[(((size_t)(b * 9 + tap)) * CO + cp * 2 + cl) * CI + cin] =
            __float2half(tw[cl * 1152 + cin * 9 + tap]);
}

// ---- conv smem layout (bytes) ----
static constexpr int XS_PER   = 49152;                 // 32 cin x 6 rows x 16 segs x 16B
static constexpr int XS_OFF   = 0;                     // 2 buffers
static constexpr int A_OFF    = 2 * XS_PER;            // 98304; 3 buffers x 10240
static constexpr int A_PER    = 10240;                 // 128 x 40 halves
static constexpr int B_OFF    = A_OFF + 3 * A_PER;     // 129024
static constexpr int B_BYTES  = 20480;                 // 256 x 40 halves
static constexpr int SMEM_BYTES = B_OFF + B_BYTES;     // 149504

__global__ __launch_bounds__(512, 1) void conv_kernel(const float* __restrict__ x,
                                                      float* __restrict__ out) {
    extern __shared__ char smc[];
    const uint32_t sb = smem_u32(smc);
    const int tid = threadIdx.x, wid = tid >> 5, lane = tid & 31;
    const int nt = blockIdx.x, b = blockIdx.y;
    const int h4 = nt << 2;                            // 4 image rows / CTA
    const int mb = (wid & 1) << 6;                     // warp grid 2m x 8n
    const int nb = (wid >> 1) << 5;                    // warp tile 64 x 32
    const int qid = lane >> 2, tig = lane & 3;

    const int ar16 = ((lane >> 3) & 1) * 8 + (lane & 7);
    const int akh  = (lane >> 4) & 1;
    const int br16 = ((lane >> 4) & 1) * 8 + (lane & 7);
    const int bkh  = (lane >> 3) & 1;

    const int bk = lane & 15;                          // build: cin-in-16
    const int bnh = lane >> 4;                         // build: n-half

    float acc[4][4][4];
#pragma unroll
    for (int f = 0; f < 4; f++)
#pragma unroll
        for (int j = 0; j < 4; j++)
#pragma unroll
            for (int c = 0; c < 4; c++) acc[f][j][c] = 0.f;

    // stage fp32 input chunk c (32 cins, rows h4-1..h4+4, zfill OOB rows)
    auto issueX = [&](int c) {
        if (c > 3) return;
        const uint32_t xbase = sb + (uint32_t)((c & 1) * XS_PER);
        const float* srcb = x + ((size_t)(b * CI + c * 32)) * HW;
#pragma unroll
        for (int i = 0; i < 6; ++i) {
            int idx = tid + (i << 9);                  // 0..3071
            int cin = idx / 96, rem = idx - cin * 96;
            int row = rem >> 4, seg = rem & 15;
            int hg = h4 - 1 + row;
            bool ok = (unsigned)hg < 64u;
            int hc = ok ? hg : 0;
            int sz = ok ? 16 : 0;
            uint32_t d = xbase + (uint32_t)((cin * 96 + row * 16 + (seg ^ (cin & 15))) << 4);
            const float* g = srcb + (size_t)cin * HW + hc * 64 + seg * 4;
            asm volatile("cp.async.cg.shared.global [%0], [%1], 16, %2;"
                         :: "r"(d), "l"(g), "r"(sz) : "memory");
        }
    };
    // weight tile for iteration it2 (tap, cin chunk), fp16, 1 cp.async/thread
    auto issueA = [&](int it2) {
        if (it2 > 35) return;
        int c2 = it2 / 9, tap2 = it2 - c2 * 9;
        const __half* g = g_wt + (((size_t)(b * 9 + tap2)) * CO + (tid >> 2)) * CI
                          + c2 * 32 + (tid & 3) * 8;
        uint32_t d = sb + A_OFF + (uint32_t)((it2 % 3) * A_PER)
                     + (uint32_t)(((tid >> 2) * 40 + (tid & 3) * 8) * 2);
        asm volatile("cp.async.cg.shared.global [%0], [%1], 16;"
                     :: "r"(d), "l"(g) : "memory");
    };

    issueX(0); issueA(0); asm volatile("cp.async.commit_group;" ::: "memory");
    issueX(1); issueA(1); asm volatile("cp.async.commit_group;" ::: "memory");

    for (int it = 0; it < 36; ++it) {
        const int c = it / 9, tap = it - c * 9;
        asm volatile("cp.async.wait_group 1;" ::: "memory");
        __syncthreads();                                // A(it), Xs(c) ready; B free

        // ---- build fp16 B tile [256 n][32 k] for this tap from staged fp32 ----
        {
            const int r_ = tap / 3 - 1, s_ = tap % 3 - 1;
            const uint32_t xb_ = sb + (uint32_t)((c & 1) * XS_PER);
#pragma unroll
            for (int i = 0; i < 16; ++i) {
                int gstep = wid * 16 + i;               // 0..255
                int khalf = gstep >> 7, p = gstep & 127;
                int n = (p << 1) + bnh;
                int kk = bk + (khalf << 4);             // 0..31
                int row = (n >> 6) + 1 + r_;            // 0..5
                int wp = (n & 63) + s_;
                float v = 0.f;
                if ((unsigned)wp < 64u) {
                    uint32_t a_ = xb_ + (uint32_t)(kk * 1536 + row * 256
                                   + (((wp >> 2) ^ bk) << 4) + (wp & 3) * 4);
                    asm volatile("ld.shared.f32 %0, [%1];" : "=f"(v) : "r"(a_));
                }
                unsigned short hv = __half_as_ushort(__float2half(v));
                uint32_t d_ = sb + B_OFF + (uint32_t)((n * 40 + kk) * 2);
                asm volatile("st.shared.u16 [%0], %1;" :: "r"(d_), "h"(hv));
            }
        }
        __syncthreads();                                // B complete; prev reads done

        issueA(it + 2);
        if (tap == 8) issueX(c + 2);
        asm volatile("cp.async.commit_group;" ::: "memory");

        // ---- MMA: K=32 (two k16 slices), warp tile 64x32 ----
        const uint32_t a0 = sb + A_OFF + (uint32_t)((it % 3) * A_PER)
                            + (uint32_t)(((mb + ar16) * 40 + akh * 8) * 2);
        const uint32_t b0 = sb + B_OFF + (uint32_t)(((nb + br16) * 40 + bkh * 8) * 2);
#pragma unroll
        for (int ks = 0; ks < 2; ++ks) {
            uint32_t a[4][4], bq[2][4];
#pragma unroll
            for (int f = 0; f < 4; ++f)
                ldm_x4(a[f], a0 + (uint32_t)((f * 16 * 40 + ks * 16) * 2));
#pragma unroll
            for (int jj = 0; jj < 2; ++jj)
                ldm_x4(bq[jj], b0 + (uint32_t)((jj * 16 * 40 + ks * 16) * 2));
#pragma unroll
            for (int f = 0; f < 4; ++f)
#pragma unroll
                for (int jj = 0; jj < 2; ++jj) {
                    asm volatile(
                        "mma.sync.aligned.m16n8k16.row.col.f32.f16.f16.f32 "
                        "{%0,%1,%2,%3}, {%4,%5,%6,%7}, {%8,%9}, {%0,%1,%2,%3};"
                        : "+f"(acc[f][2 * jj][0]), "+f"(acc[f][2 * jj][1]),
                          "+f"(acc[f][2 * jj][2]), "+f"(acc[f][2 * jj][3])
                        : "r"(a[f][0]), "r"(a[f][1]), "r"(a[f][2]), "r"(a[f][3]),
                          "r"(bq[jj][0]), "r"(bq[jj][1]));
                    asm volatile(
                        "mma.sync.aligned.m16n8k16.row.col.f32.f16.f16.f32 "
                        "{%0,%1,%2,%3}, {%4,%5,%6,%7}, {%8,%9}, {%0,%1,%2,%3};"
                        : "+f"(acc[f][2 * jj + 1][0]), "+f"(acc[f][2 * jj + 1][1]),
                          "+f"(acc[f][2 * jj + 1][2]), "+f"(acc[f][2 * jj + 1][3])
                        : "r"(a[f][0]), "r"(a[f][1]), "r"(a[f][2]), "r"(a[f][3]),
                          "r"(bq[jj][2]), "r"(bq[jj][3]));
                }
        }
    }

    // ---- epilogue: warp covers 64 m x 32 n of the 128x256 tile ----
#pragma unroll
    for (int f = 0; f < 4; ++f) {
        int co = mb + 16 * f + qid;
        float* o0 = out + ((size_t)(b * CO + co)) * HW + (nt << 8) + nb + 2 * tig;
        float* o1 = o0 + 8 * HW;
#pragma unroll
        for (int j = 0; j < 4; ++j) {
            *(float2*)(o0 + 8 * j) = make_float2(acc[f][j][0], acc[f][j][1]);
            *(float2*)(o1 + 8 * j) = make_float2(acc[f][j][2], acc[f][j][3]);
        }
    }
}

extern "C" void kernel_launch(void* const* d_in, const int* in_sizes, int n_in,
                              void* d_out, int out_size) {
    const float* feat = (const float*)d_in[0];   // (16,128,64,64)
    const float* wker = (const float*)d_in[1];   // (16,128,128,3,3)
    float* out = (float*)d_out;

    cudaFuncSetAttribute(conv_kernel, cudaFuncAttributeMaxDynamicSharedMemorySize, SMEM_BYTES);

    prep_w<<<dim3(64, BB), 256>>>(wker);
    conv_kernel<<<dim3(16, BB), 512, SMEM_BYTES>>>(feat, out);
}

// round 15
// speedup vs baseline: 1.7197x; 1.7197x over previous
#include <cuda_runtime.h>
#include <cuda_fp16.h>
#include <cstdint>

// DynamicConvolution: B=16, Cin=Cout=128, K=3, H=W=64, pad=1, fp32.
// R14: R13 + fix: convert() computes the odd-channel smem address from the
// full swizzle expression (R13's additive XOR-delta was wrong for odd w>>2).
// No input pre-pass: stage fp32 NCHW chunk (cp.async, h-halo zfill), convert
// to NHWC fp16 once per cin-chunk, per-tap B fragments via ldmatrix with
// per-lane shifted row addresses (OOB -> zero row). fp16 m16n8k16, 512 thr.

#define BB 16
#define CI 128
#define CO 128
#define HW 4096

__device__ __half g_wt[(size_t)BB * 9 * CO * CI];  // [b][rs][cout][cin] fp16

__device__ __forceinline__ uint32_t smem_u32(const void* p) {
    uint32_t a; asm("{ .reg .u64 t; cvta.to.shared.u64 t, %1; cvt.u32.u64 %0, t; }" : "=r"(a) : "l"(p));
    return a;
}
__device__ __forceinline__ void ldm_x4(uint32_t* r, uint32_t addr) {
    asm volatile("ldmatrix.sync.aligned.m8n8.x4.shared.b16 {%0,%1,%2,%3}, [%4];"
                 : "=r"(r[0]), "=r"(r[1]), "=r"(r[2]), "=r"(r[3]) : "r"(addr));
}

// ---- weight repack: [b][cout][cin][rs] -> [b][rs][cout][cin] fp16, 1024 blocks ----
__global__ __launch_bounds__(256) void prep_w(const float* __restrict__ w) {
    __shared__ float tw[2 * 1152];
    const int cp = blockIdx.x, b = blockIdx.y;          // cout pair
    const float* src = w + ((size_t)(b * CO + cp * 2)) * 1152;
#pragma unroll
    for (int i = 0; i < 9; ++i) tw[threadIdx.x + i * 256] = src[threadIdx.x + i * 256];
    __syncthreads();
    const int cl = threadIdx.x >> 7, cin = threadIdx.x & 127;
#pragma unroll
    for (int tap = 0; tap < 9; ++tap)
        g_wt[(((size_t)(b * 9 + tap)) * CO + cp * 2 + cl) * CI + cin] =
            __float2half(tw[cl * 1152 + cin * 9 + tap]);
}

// ---- conv smem layout (bytes) ----
static constexpr int XS_PER   = 49152;                 // 32 cin x 6 rows x 16 segs x 16B
static constexpr int A_OFF    = 2 * XS_PER;            // 98304
static constexpr int A_PER    = 10240;                 // 128 x 40 halves
static constexpr int NHWC_OFF = A_OFF + 3 * A_PER;     // 129024; 384 pos x 40 halves
static constexpr int NHWC_BYTES = 384 * 80;            // 30720
static constexpr int ZERO_OFF = NHWC_OFF + NHWC_BYTES; // 159744; 64B zeros
static constexpr int SMEM_BYTES = ZERO_OFF + 64;       // 159808

__global__ __launch_bounds__(512, 1) void conv_kernel(const float* __restrict__ x,
                                                      float* __restrict__ out) {
    extern __shared__ char smc[];
    const uint32_t sb = smem_u32(smc);
    const int tid = threadIdx.x, wid = tid >> 5, lane = tid & 31;
    const int nt = blockIdx.x, b = blockIdx.y;
    const int h4 = nt << 2;                            // 4 image rows / CTA
    const int mb = (wid & 1) << 6;                     // warp grid 2m x 8n
    const int nb = (wid >> 1) << 5;                    // warp tile 64 x 32
    const int qid = lane >> 2, tig = lane & 3;

    const int ar16 = ((lane >> 3) & 1) * 8 + (lane & 7);
    const int akh  = (lane >> 4) & 1;
    const int br16 = ((lane >> 4) & 1) * 8 + (lane & 7);
    const int bkh  = (lane >> 3) & 1;

    // zero row for OOB ldmatrix lanes
    if (tid < 16) {
        uint32_t z = sb + ZERO_OFF + tid * 4;
        asm volatile("st.shared.u32 [%0], %1;" :: "r"(z), "r"(0u));
    }

    float acc[4][4][4];
#pragma unroll
    for (int f = 0; f < 4; f++)
#pragma unroll
        for (int j = 0; j < 4; j++)
#pragma unroll
            for (int c = 0; c < 4; c++) acc[f][j][c] = 0.f;

    // stage fp32 input chunk c (32 cins, rows h4-1..h4+4, zfill OOB rows)
    auto issueX = [&](int c) {
        if (c > 3) return;
        const uint32_t xbase = sb + (uint32_t)((c & 1) * XS_PER);
        const float* srcb = x + ((size_t)(b * CI + c * 32)) * HW;
#pragma unroll
        for (int i = 0; i < 6; ++i) {
            int idx = tid + (i << 9);                  // 0..3071
            int cin = idx / 96, rem = idx - cin * 96;
            int row = rem >> 4, seg = rem & 15;
            int hg = h4 - 1 + row;
            bool ok = (unsigned)hg < 64u;
            int hc = ok ? hg : 0;
            int sz = ok ? 16 : 0;
            uint32_t d = xbase + (uint32_t)((cin * 96 + row * 16 + (seg ^ (cin & 15))) << 4);
            const float* g = srcb + (size_t)cin * HW + hc * 64 + seg * 4;
            asm volatile("cp.async.cg.shared.global [%0], [%1], 16, %2;"
                         :: "r"(d), "l"(g), "r"(sz) : "memory");
        }
    };
    // weight tile (tap, cin chunk), fp16, 1 cp.async/thread
    auto issueA = [&](int it2) {
        if (it2 > 35) return;
        int c2 = it2 / 9, tap2 = it2 - c2 * 9;
        const __half* g = g_wt + (((size_t)(b * 9 + tap2)) * CO + (tid >> 2)) * CI
                          + c2 * 32 + (tid & 3) * 8;
        uint32_t d = sb + A_OFF + (uint32_t)((it2 % 3) * A_PER)
                     + (uint32_t)(((tid >> 2) * 40 + (tid & 3) * 8) * 2);
        asm volatile("cp.async.cg.shared.global [%0], [%1], 16;"
                     :: "r"(d), "l"(g) : "memory");
    };
    // fp32 staged -> NHWC fp16 staging, once per chunk (12 half2 per thread)
    auto convert = [&](int c) {
        const uint32_t xb_ = sb + (uint32_t)((c & 1) * XS_PER);
        const uint32_t nw_ = sb + NHWC_OFF;
#pragma unroll
        for (int i = 0; i < 12; ++i) {
            int e = (i << 9) + tid;                    // 0..6143
            int cin2 = e & 15, pos = e >> 4;           // pos = row*64 + w, 0..383
            int row = pos >> 6, w = pos & 63;
            int c0 = cin2 << 1, c1 = c0 + 1;
            float v0, v1;
            uint32_t a0_ = xb_ + (uint32_t)(c0 * 1536 + row * 256
                           + (((w >> 2) ^ (c0 & 15)) << 4) + (w & 3) * 4);
            uint32_t a1_ = xb_ + (uint32_t)(c1 * 1536 + row * 256
                           + (((w >> 2) ^ (c1 & 15)) << 4) + (w & 3) * 4);
            asm volatile("ld.shared.f32 %0, [%1];" : "=f"(v0) : "r"(a0_));
            asm volatile("ld.shared.f32 %0, [%1];" : "=f"(v1) : "r"(a1_));
            __half2 hv = __floats2half2_rn(v0, v1);
            uint32_t d_ = nw_ + (uint32_t)(pos * 80 + cin2 * 4);
            asm volatile("st.shared.u32 [%0], %1;" :: "r"(d_), "r"(*(uint32_t*)&hv));
        }
    };

    issueX(0); issueA(0); asm volatile("cp.async.commit_group;" ::: "memory");
    issueX(1); issueA(1); asm volatile("cp.async.commit_group;" ::: "memory");

    for (int it = 0; it < 36; ++it) {
        const int c = it / 9, tap = it - c * 9;
        asm volatile("cp.async.wait_group 1;" ::: "memory");
        __syncthreads();                                // A(it) ready; Xs(c) ready
        if (tap == 0) {
            convert(c);
            __syncthreads();                            // NHWC staging complete
        }
        issueA(it + 2);
        if (tap == 8) issueX(c + 2);
        asm volatile("cp.async.commit_group;" ::: "memory");

        // per-lane B row addresses for this tap (OOB w -> zero row)
        const int r_ = tap / 3 - 1, s_ = tap % 3 - 1;
        uint32_t baddr[2];
#pragma unroll
        for (int jj = 0; jj < 2; ++jj) {
            int n = nb + jj * 16 + br16;
            int hrow = (n >> 6) + 1 + r_;               // 0..5, staged
            int wp = (n & 63) + s_;
            bool ok = (unsigned)wp < 64u;
            baddr[jj] = ok ? sb + NHWC_OFF + (uint32_t)((hrow * 64 + wp) * 80 + bkh * 16)
                           : sb + ZERO_OFF + (uint32_t)(bkh * 16);
        }
        const uint32_t a0 = sb + A_OFF + (uint32_t)((it % 3) * A_PER)
                            + (uint32_t)(((mb + ar16) * 40 + akh * 8) * 2);
#pragma unroll
        for (int ks = 0; ks < 2; ++ks) {
            uint32_t a[4][4], bq[2][4];
#pragma unroll
            for (int f = 0; f < 4; ++f)
                ldm_x4(a[f], a0 + (uint32_t)((f * 16 * 40 + ks * 16) * 2));
#pragma unroll
            for (int jj = 0; jj < 2; ++jj)
                ldm_x4(bq[jj], baddr[jj] + (uint32_t)(ks * 32));
#pragma unroll
            for (int f = 0; f < 4; ++f)
#pragma unroll
                for (int jj = 0; jj < 2; ++jj) {
                    asm volatile(
                        "mma.sync.aligned.m16n8k16.row.col.f32.f16.f16.f32 "
                        "{%0,%1,%2,%3}, {%4,%5,%6,%7}, {%8,%9}, {%0,%1,%2,%3};"
                        : "+f"(acc[f][2 * jj][0]), "+f"(acc[f][2 * jj][1]),
                          "+f"(acc[f][2 * jj][2]), "+f"(acc[f][2 * jj][3])
                        : "r"(a[f][0]), "r"(a[f][1]), "r"(a[f][2]), "r"(a[f][3]),
                          "r"(bq[jj][0]), "r"(bq[jj][1]));
                    asm volatile(
                        "mma.sync.aligned.m16n8k16.row.col.f32.f16.f16.f32 "
                        "{%0,%1,%2,%3}, {%4,%5,%6,%7}, {%8,%9}, {%0,%1,%2,%3};"
                        : "+f"(acc[f][2 * jj + 1][0]), "+f"(acc[f][2 * jj + 1][1]),
                          "+f"(acc[f][2 * jj + 1][2]), "+f"(acc[f][2 * jj + 1][3])
                        : "r"(a[f][0]), "r"(a[f][1]), "r"(a[f][2]), "r"(a[f][3]),
                          "r"(bq[jj][2]), "r"(bq[jj][3]));
                }
        }
    }

    // epilogue: warp covers 64 m x 32 n of the 128x256 tile
#pragma unroll
    for (int f = 0; f < 4; ++f) {
        int co = mb + 16 * f + qid;
        float* o0 = out + ((size_t)(b * CO + co)) * HW + (nt << 8) + nb + 2 * tig;
        float* o1 = o0 + 8 * HW;
#pragma unroll
        for (int j = 0; j < 4; ++j) {
            *(float2*)(o0 + 8 * j) = make_float2(acc[f][j][0], acc[f][j][1]);
            *(float2*)(o1 + 8 * j) = make_float2(acc[f][j][2], acc[f][j][3]);
        }
    }
}

extern "C" void kernel_launch(void* const* d_in, const int* in_sizes, int n_in,
                              void* d_out, int out_size) {
    const float* feat = (const float*)d_in[0];   // (16,128,64,64)
    const float* wker = (const float*)d_in[1];   // (16,128,128,3,3)
    float* out = (float*)d_out;

    cudaFuncSetAttribute(conv_kernel, cudaFuncAttributeMaxDynamicSharedMemorySize, SMEM_BYTES);

    prep_w<<<dim3(64, BB), 256>>>(wker);
    conv_kernel<<<dim3(16, BB), 512, SMEM_BYTES>>>(feat, out);
}

// round 16
// speedup vs baseline: 1.7242x; 1.0027x over previous
#include <cuda_runtime.h>
#include <cuda_fp16.h>
#include <cstdint>

// DynamicConvolution: B=16, Cin=Cout=128, K=3, H=W=64, pad=1, fp32.
// R15: R14 + convert-ahead pipelining. NHWC fp16 staging is double-buffered;
// chunk c+1's fp32->fp16 conversion runs 2 slices/tap during chunk c's taps
// 0..5, hidden behind MMAs. issueX(c+2) moved to tap 0 (buffer free + gives
// the copy 9 taps before its convert). Prologue converts chunk 0 once.

#define BB 16
#define CI 128
#define CO 128
#define HW 4096

__device__ __half g_wt[(size_t)BB * 9 * CO * CI];  // [b][rs][cout][cin] fp16

__device__ __forceinline__ uint32_t smem_u32(const void* p) {
    uint32_t a; asm("{ .reg .u64 t; cvta.to.shared.u64 t, %1; cvt.u32.u64 %0, t; }" : "=r"(a) : "l"(p));
    return a;
}
__device__ __forceinline__ void ldm_x4(uint32_t* r, uint32_t addr) {
    asm volatile("ldmatrix.sync.aligned.m8n8.x4.shared.b16 {%0,%1,%2,%3}, [%4];"
                 : "=r"(r[0]), "=r"(r[1]), "=r"(r[2]), "=r"(r[3]) : "r"(addr));
}

// ---- weight repack: [b][cout][cin][rs] -> [b][rs][cout][cin] fp16 ----
__global__ __launch_bounds__(256) void prep_w(const float* __restrict__ w) {
    __shared__ float tw[2 * 1152];
    const int cp = blockIdx.x, b = blockIdx.y;          // cout pair
    const float* src = w + ((size_t)(b * CO + cp * 2)) * 1152;
#pragma unroll
    for (int i = 0; i < 9; ++i) tw[threadIdx.x + i * 256] = src[threadIdx.x + i * 256];
    __syncthreads();
    const int cl = threadIdx.x >> 7, cin = threadIdx.x & 127;
#pragma unroll
    for (int tap = 0; tap < 9; ++tap)
        g_wt[(((size_t)(b * 9 + tap)) * CO + cp * 2 + cl) * CI + cin] =
            __float2half(tw[cl * 1152 + cin * 9 + tap]);
}

// ---- conv smem layout (bytes) ----
static constexpr int XS_PER   = 49152;                 // 32 cin x 6 rows x 16 segs x 16B
static constexpr int A_OFF    = 2 * XS_PER;            // 98304
static constexpr int A_PER    = 10240;                 // 128 x 40 halves
static constexpr int NHWC_OFF = A_OFF + 3 * A_PER;     // 129024
static constexpr int NHWC_BYTES = 384 * 80;            // 30720, x2 buffers
static constexpr int ZERO_OFF = NHWC_OFF + 2 * NHWC_BYTES;  // 190464
static constexpr int SMEM_BYTES = ZERO_OFF + 64;       // 190528

__global__ __launch_bounds__(512, 1) void conv_kernel(const float* __restrict__ x,
                                                      float* __restrict__ out) {
    extern __shared__ char smc[];
    const uint32_t sb = smem_u32(smc);
    const int tid = threadIdx.x, wid = tid >> 5, lane = tid & 31;
    const int nt = blockIdx.x, b = blockIdx.y;
    const int h4 = nt << 2;                            // 4 image rows / CTA
    const int mb = (wid & 1) << 6;                     // warp grid 2m x 8n
    const int nb = (wid >> 1) << 5;                    // warp tile 64 x 32
    const int qid = lane >> 2, tig = lane & 3;

    const int ar16 = ((lane >> 3) & 1) * 8 + (lane & 7);
    const int akh  = (lane >> 4) & 1;
    const int br16 = ((lane >> 4) & 1) * 8 + (lane & 7);
    const int bkh  = (lane >> 3) & 1;

    if (tid < 16) {                                    // zero row for OOB lanes
        uint32_t z = sb + ZERO_OFF + tid * 4;
        asm volatile("st.shared.u32 [%0], %1;" :: "r"(z), "r"(0u));
    }

    float acc[4][4][4];
#pragma unroll
    for (int f = 0; f < 4; f++)
#pragma unroll
        for (int j = 0; j < 4; j++)
#pragma unroll
            for (int c = 0; c < 4; c++) acc[f][j][c] = 0.f;

    // stage fp32 input chunk c (32 cins, rows h4-1..h4+4, zfill OOB rows)
    auto issueX = [&](int c) {
        if (c > 3) return;
        const uint32_t xbase = sb + (uint32_t)((c & 1) * XS_PER);
        const float* srcb = x + ((size_t)(b * CI + c * 32)) * HW;
#pragma unroll
        for (int i = 0; i < 6; ++i) {
            int idx = tid + (i << 9);                  // 0..3071
            int cin = idx / 96, rem = idx - cin * 96;
            int row = rem >> 4, seg = rem & 15;
            int hg = h4 - 1 + row;
            bool ok = (unsigned)hg < 64u;
            int hc = ok ? hg : 0;
            int sz = ok ? 16 : 0;
            uint32_t d = xbase + (uint32_t)((cin * 96 + row * 16 + (seg ^ (cin & 15))) << 4);
            const float* g = srcb + (size_t)cin * HW + hc * 64 + seg * 4;
            asm volatile("cp.async.cg.shared.global [%0], [%1], 16, %2;"
                         :: "r"(d), "l"(g), "r"(sz) : "memory");
        }
    };
    // weight tile (tap, cin chunk), fp16, 1 cp.async/thread
    auto issueA = [&](int it2) {
        if (it2 > 35) return;
        int c2 = it2 / 9, tap2 = it2 - c2 * 9;
        const __half* g = g_wt + (((size_t)(b * 9 + tap2)) * CO + (tid >> 2)) * CI
                          + c2 * 32 + (tid & 3) * 8;
        uint32_t d = sb + A_OFF + (uint32_t)((it2 % 3) * A_PER)
                     + (uint32_t)(((tid >> 2) * 40 + (tid & 3) * 8) * 2);
        asm volatile("cp.async.cg.shared.global [%0], [%1], 16;"
                     :: "r"(d), "l"(g) : "memory");
    };
    // one slice (1/12) of fp32 staged -> NHWC fp16 for chunk c
    auto convert_slice = [&](int c, int i) {
        const uint32_t xb_ = sb + (uint32_t)((c & 1) * XS_PER);
        const uint32_t nw_ = sb + NHWC_OFF + (uint32_t)((c & 1) * NHWC_BYTES);
        int e = (i << 9) + tid;                        // 0..6143
        int cin2 = e & 15, pos = e >> 4;               // pos = row*64 + w
        int row = pos >> 6, w = pos & 63;
        int c0 = cin2 << 1, c1 = c0 + 1;
        float v0, v1;
        uint32_t a0_ = xb_ + (uint32_t)(c0 * 1536 + row * 256
                       + (((w >> 2) ^ (c0 & 15)) << 4) + (w & 3) * 4);
        uint32_t a1_ = xb_ + (uint32_t)(c1 * 1536 + row * 256
                       + (((w >> 2) ^ (c1 & 15)) << 4) + (w & 3) * 4);
        asm volatile("ld.shared.f32 %0, [%1];" : "=f"(v0) : "r"(a0_));
        asm volatile("ld.shared.f32 %0, [%1];" : "=f"(v1) : "r"(a1_));
        __half2 hv = __floats2half2_rn(v0, v1);
        uint32_t d_ = nw_ + (uint32_t)(pos * 80 + cin2 * 4);
        asm volatile("st.shared.u32 [%0], %1;" :: "r"(d_), "r"(*(uint32_t*)&hv));
    };

    // ---- prologue: stage X0,X1; convert chunk 0; prime A pipeline ----
    issueX(0); asm volatile("cp.async.commit_group;" ::: "memory");
    issueX(1); issueA(0); asm volatile("cp.async.commit_group;" ::: "memory");
    asm volatile("cp.async.wait_group 1;" ::: "memory");   // Xs(0) ready
    __syncthreads();
#pragma unroll
    for (int i = 0; i < 12; ++i) convert_slice(0, i);
    __syncthreads();
    issueA(1); asm volatile("cp.async.commit_group;" ::: "memory");

    for (int it = 0; it < 36; ++it) {
        const int c = it / 9, tap = it - c * 9;
        asm volatile("cp.async.wait_group 1;" ::: "memory");
        __syncthreads();                               // A(it) ready; converts visible

        issueA(it + 2);
        if (tap == 0) issueX(c + 2);                   // buffer c&1 dead after convert(c)
        asm volatile("cp.async.commit_group;" ::: "memory");

        // convert-ahead: 2 slices/tap of chunk c+1 during taps 0..5
        if (c < 3 && tap < 6) {
            convert_slice(c + 1, 2 * tap);
            convert_slice(c + 1, 2 * tap + 1);
        }

        // per-lane B row addresses for this tap (OOB w -> zero row)
        const int r_ = tap / 3 - 1, s_ = tap % 3 - 1;
        const uint32_t nwb = sb + NHWC_OFF + (uint32_t)((c & 1) * NHWC_BYTES);
        uint32_t baddr[2];
#pragma unroll
        for (int jj = 0; jj < 2; ++jj) {
            int n = nb + jj * 16 + br16;
            int hrow = (n >> 6) + 1 + r_;
            int wp = (n & 63) + s_;
            bool ok = (unsigned)wp < 64u;
            baddr[jj] = ok ? nwb + (uint32_t)((hrow * 64 + wp) * 80 + bkh * 16)
                           : sb + ZERO_OFF + (uint32_t)(bkh * 16);
        }
        const uint32_t a0 = sb + A_OFF + (uint32_t)((it % 3) * A_PER)
                            + (uint32_t)(((mb + ar16) * 40 + akh * 8) * 2);
#pragma unroll
        for (int ks = 0; ks < 2; ++ks) {
            uint32_t a[4][4], bq[2][4];
#pragma unroll
            for (int f = 0; f < 4; ++f)
                ldm_x4(a[f], a0 + (uint32_t)((f * 16 * 40 + ks * 16) * 2));
#pragma unroll
            for (int jj = 0; jj < 2; ++jj)
                ldm_x4(bq[jj], baddr[jj] + (uint32_t)(ks * 32));
#pragma unroll
            for (int f = 0; f < 4; ++f)
#pragma unroll
                for (int jj = 0; jj < 2; ++jj) {
                    asm volatile(
                        "mma.sync.aligned.m16n8k16.row.col.f32.f16.f16.f32 "
                        "{%0,%1,%2,%3}, {%4,%5,%6,%7}, {%8,%9}, {%0,%1,%2,%3};"
                        : "+f"(acc[f][2 * jj][0]), "+f"(acc[f][2 * jj][1]),
                          "+f"(acc[f][2 * jj][2]), "+f"(acc[f][2 * jj][3])
                        : "r"(a[f][0]), "r"(a[f][1]), "r"(a[f][2]), "r"(a[f][3]),
                          "r"(bq[jj][0]), "r"(bq[jj][1]));
                    asm volatile(
                        "mma.sync.aligned.m16n8k16.row.col.f32.f16.f16.f32 "
                        "{%0,%1,%2,%3}, {%4,%5,%6,%7}, {%8,%9}, {%0,%1,%2,%3};"
                        : "+f"(acc[f][2 * jj + 1][0]), "+f"(acc[f][2 * jj + 1][1]),
                          "+f"(acc[f][2 * jj + 1][2]), "+f"(acc[f][2 * jj + 1][3])
                        : "r"(a[f][0]), "r"(a[f][1]), "r"(a[f][2]), "r"(a[f][3]),
                          "r"(bq[jj][2]), "r"(bq[jj][3]));
                }
        }
    }

    // epilogue: warp covers 64 m x 32 n of the 128x256 tile
#pragma unroll
    for (int f = 0; f < 4; ++f) {
        int co = mb + 16 * f + qid;
        float* o0 = out + ((size_t)(b * CO + co)) * HW + (nt << 8) + nb + 2 * tig;
        float* o1 = o0 + 8 * HW;
#pragma unroll
        for (int j = 0; j < 4; ++j) {
            *(float2*)(o0 + 8 * j) = make_float2(acc[f][j][0], acc[f][j][1]);
            *(float2*)(o1 + 8 * j) = make_float2(acc[f][j][2], acc[f][j][3]);
        }
    }
}

extern "C" void kernel_launch(void* const* d_in, const int* in_sizes, int n_in,
                              void* d_out, int out_size) {
    const float* feat = (const float*)d_in[0];   // (16,128,64,64)
    const float* wker = (const float*)d_in[1];   // (16,128,128,3,3)
    float* out = (float*)d_out;

    cudaFuncSetAttribute(conv_kernel, cudaFuncAttributeMaxDynamicSharedMemorySize, SMEM_BYTES);

    prep_w<<<dim3(64, BB), 256>>>(wker);
    conv_kernel<<<dim3(16, BB), 512, SMEM_BYTES>>>(feat, out);
}

// round 17
// speedup vs baseline: 2.0195x; 1.1713x over previous
#include <cuda_runtime.h>
#include <cuda_fp16.h>
#include <cstdint>

// DynamicConvolution: B=16, Cin=Cout=128, K=3, H=W=64, pad=1, fp32.
// R16: R15 with the mainloop restructured as c(4) x unrolled tap(9) so all
// per-iteration index math (stage = tap%3, tap shifts r/s, convert slice ids,
// issueA targets) folds to compile time; thread-invariant convert/fragment
// address parts hoisted. Same layouts, schedule, and arithmetic as R15.

#define BB 16
#define CI 128
#define CO 128
#define HW 4096

__device__ __half g_wt[(size_t)BB * 9 * CO * CI];  // [b][rs][cout][cin] fp16

__device__ __forceinline__ uint32_t smem_u32(const void* p) {
    uint32_t a; asm("{ .reg .u64 t; cvta.to.shared.u64 t, %1; cvt.u32.u64 %0, t; }" : "=r"(a) : "l"(p));
    return a;
}
__device__ __forceinline__ void ldm_x4(uint32_t* r, uint32_t addr) {
    asm volatile("ldmatrix.sync.aligned.m8n8.x4.shared.b16 {%0,%1,%2,%3}, [%4];"
                 : "=r"(r[0]), "=r"(r[1]), "=r"(r[2]), "=r"(r[3]) : "r"(addr));
}

// ---- weight repack: [b][cout][cin][rs] -> [b][rs][cout][cin] fp16 ----
__global__ __launch_bounds__(256) void prep_w(const float* __restrict__ w) {
    __shared__ float tw[2 * 1152];
    const int cp = blockIdx.x, b = blockIdx.y;          // cout pair
    const float* src = w + ((size_t)(b * CO + cp * 2)) * 1152;
#pragma unroll
    for (int i = 0; i < 9; ++i) tw[threadIdx.x + i * 256] = src[threadIdx.x + i * 256];
    __syncthreads();
    const int cl = threadIdx.x >> 7, cin = threadIdx.x & 127;
#pragma unroll
    for (int tap = 0; tap < 9; ++tap)
        g_wt[(((size_t)(b * 9 + tap)) * CO + cp * 2 + cl) * CI + cin] =
            __float2half(tw[cl * 1152 + cin * 9 + tap]);
}

// ---- conv smem layout (bytes) ----
static constexpr int XS_PER   = 49152;                 // 32 cin x 6 rows x 16 segs x 16B
static constexpr int A_OFF    = 2 * XS_PER;            // 98304
static constexpr int A_PER    = 10240;                 // 128 x 40 halves
static constexpr int NHWC_OFF = A_OFF + 3 * A_PER;     // 129024
static constexpr int NHWC_BYTES = 384 * 80;            // 30720, x2 buffers
static constexpr int ZERO_OFF = NHWC_OFF + 2 * NHWC_BYTES;  // 190464
static constexpr int SMEM_BYTES = ZERO_OFF + 64;       // 190528

__global__ __launch_bounds__(512, 1) void conv_kernel(const float* __restrict__ x,
                                                      float* __restrict__ out) {
    extern __shared__ char smc[];
    const uint32_t sb = smem_u32(smc);
    const int tid = threadIdx.x, wid = tid >> 5, lane = tid & 31;
    const int nt = blockIdx.x, b = blockIdx.y;
    const int h4 = nt << 2;                            // 4 image rows / CTA
    const int mb = (wid & 1) << 6;                     // warp grid 2m x 8n
    const int nb = (wid >> 1) << 5;                    // warp tile 64 x 32
    const int qid = lane >> 2, tig = lane & 3;

    const int ar16 = ((lane >> 3) & 1) * 8 + (lane & 7);
    const int akh  = (lane >> 4) & 1;
    const int br16 = ((lane >> 4) & 1) * 8 + (lane & 7);
    const int bkh  = (lane >> 3) & 1;

    // hoisted thread-invariant params
    const uint32_t a_toff = (uint32_t)(((mb + ar16) * 40 + akh * 8) * 2);  // A frag offset
    int nw_[2], nh_[2];                                 // B frag: w-in-row, hrow base
#pragma unroll
    for (int jj = 0; jj < 2; ++jj) {
        int n = nb + jj * 16 + br16;
        nw_[jj] = n & 63;
        nh_[jj] = (n >> 6) + 1;
    }
    const uint32_t zaddr = sb + ZERO_OFF + (uint32_t)(bkh * 16);
    // convert lane params (slice-invariant: 512 = 0 mod 16)
    const int cv_cin2 = tid & 15, cv_p0 = tid >> 4;
    const int cv_c0 = cv_cin2 << 1, cv_c1 = cv_c0 + 1;

    if (tid < 16) {                                    // zero row for OOB lanes
        uint32_t z = sb + ZERO_OFF + tid * 4;
        asm volatile("st.shared.u32 [%0], %1;" :: "r"(z), "r"(0u));
    }

    float acc[4][4][4];
#pragma unroll
    for (int f = 0; f < 4; f++)
#pragma unroll
        for (int j = 0; j < 4; j++)
#pragma unroll
            for (int c2 = 0; c2 < 4; c2++) acc[f][j][c2] = 0.f;

    // stage fp32 input chunk c (32 cins, rows h4-1..h4+4, zfill OOB rows)
    auto issueX = [&](int c) {
        if (c > 3) return;
        const uint32_t xbase = sb + (uint32_t)((c & 1) * XS_PER);
        const float* srcb = x + ((size_t)(b * CI + c * 32)) * HW;
#pragma unroll
        for (int i = 0; i < 6; ++i) {
            int idx = tid + (i << 9);                  // 0..3071
            int cin = idx / 96, rem = idx - cin * 96;
            int row = rem >> 4, seg = rem & 15;
            int hg = h4 - 1 + row;
            bool ok = (unsigned)hg < 64u;
            int hc = ok ? hg : 0;
            int sz = ok ? 16 : 0;
            uint32_t d = xbase + (uint32_t)((cin * 96 + row * 16 + (seg ^ (cin & 15))) << 4);
            const float* g = srcb + (size_t)cin * HW + hc * 64 + seg * 4;
            asm volatile("cp.async.cg.shared.global [%0], [%1], 16, %2;"
                         :: "r"(d), "l"(g), "r"(sz) : "memory");
        }
    };
    // weight tile (chunk cc, tap tt) into stage st
    auto issueA = [&](int cc, int tt, int st) {
        if (cc > 3) return;
        const __half* g = g_wt + (((size_t)(b * 9 + tt)) * CO + (tid >> 2)) * CI
                          + cc * 32 + (tid & 3) * 8;
        uint32_t d = sb + A_OFF + (uint32_t)(st * A_PER)
                     + (uint32_t)(((tid >> 2) * 40 + (tid & 3) * 8) * 2);
        asm volatile("cp.async.cg.shared.global [%0], [%1], 16;"
                     :: "r"(d), "l"(g) : "memory");
    };
    // one slice (1/12) of fp32 staged -> NHWC fp16 for chunk cc (i compile-time)
    auto convert_slice = [&](int cc, int i) {
        const uint32_t xb_ = sb + (uint32_t)((cc & 1) * XS_PER);
        const uint32_t nwd = sb + NHWC_OFF + (uint32_t)((cc & 1) * NHWC_BYTES);
        int pos = (i << 5) + cv_p0;                    // 0..383
        int row = pos >> 6, w = pos & 63;
        float v0, v1;
        uint32_t a0_ = xb_ + (uint32_t)(cv_c0 * 1536 + row * 256
                       + (((w >> 2) ^ (cv_c0 & 15)) << 4) + (w & 3) * 4);
        uint32_t a1_ = xb_ + (uint32_t)(cv_c1 * 1536 + row * 256
                       + (((w >> 2) ^ (cv_c1 & 15)) << 4) + (w & 3) * 4);
        asm volatile("ld.shared.f32 %0, [%1];" : "=f"(v0) : "r"(a0_));
        asm volatile("ld.shared.f32 %0, [%1];" : "=f"(v1) : "r"(a1_));
        __half2 hv = __floats2half2_rn(v0, v1);
        uint32_t d_ = nwd + (uint32_t)(pos * 80 + cv_cin2 * 4);
        asm volatile("st.shared.u32 [%0], %1;" :: "r"(d_), "r"(*(uint32_t*)&hv));
    };

    // ---- prologue: stage X0,X1; convert chunk 0; prime A pipeline ----
    issueX(0); asm volatile("cp.async.commit_group;" ::: "memory");
    issueX(1); issueA(0, 0, 0); asm volatile("cp.async.commit_group;" ::: "memory");
    asm volatile("cp.async.wait_group 1;" ::: "memory");   // Xs(0) ready
    __syncthreads();
#pragma unroll
    for (int i = 0; i < 12; ++i) convert_slice(0, i);
    __syncthreads();
    issueA(0, 1, 1); asm volatile("cp.async.commit_group;" ::: "memory");

    for (int c = 0; c < 4; ++c) {
        const uint32_t nwb = sb + NHWC_OFF + (uint32_t)((c & 1) * NHWC_BYTES);
#pragma unroll
        for (int tap = 0; tap < 9; ++tap) {
            asm volatile("cp.async.wait_group 1;" ::: "memory");
            __syncthreads();                           // A ready; converts visible

            // issue A for it+2 (compile-time tap arithmetic)
            if (tap < 7) issueA(c, tap + 2, (tap + 2) % 3);
            else         issueA(c + 1, tap - 7, (tap + 2) % 3);
            if (tap == 0) issueX(c + 2);
            asm volatile("cp.async.commit_group;" ::: "memory");

            // convert-ahead: 2 slices/tap of chunk c+1 during taps 0..5
            if (tap < 6 && c < 3) {
                convert_slice(c + 1, 2 * tap);
                convert_slice(c + 1, 2 * tap + 1);
            }

            // per-lane B row addresses (r_, s_ compile-time)
            const int r_ = tap / 3 - 1, s_ = tap % 3 - 1;
            uint32_t baddr[2];
#pragma unroll
            for (int jj = 0; jj < 2; ++jj) {
                int wp = nw_[jj] + s_;
                int hrow = nh_[jj] + r_;
                bool ok = (unsigned)wp < 64u;
                baddr[jj] = ok ? nwb + (uint32_t)((hrow * 64 + wp) * 80 + bkh * 16)
                               : zaddr;
            }
            const uint32_t a0 = sb + A_OFF + (uint32_t)((tap % 3) * A_PER) + a_toff;
#pragma unroll
            for (int ks = 0; ks < 2; ++ks) {
                uint32_t a[4][4], bq[2][4];
#pragma unroll
                for (int f = 0; f < 4; ++f)
                    ldm_x4(a[f], a0 + (uint32_t)((f * 16 * 40 + ks * 16) * 2));
#pragma unroll
                for (int jj = 0; jj < 2; ++jj)
                    ldm_x4(bq[jj], baddr[jj] + (uint32_t)(ks * 32));
#pragma unroll
                for (int f = 0; f < 4; ++f)
#pragma unroll
                    for (int jj = 0; jj < 2; ++jj) {
                        asm volatile(
                            "mma.sync.aligned.m16n8k16.row.col.f32.f16.f16.f32 "
                            "{%0,%1,%2,%3}, {%4,%5,%6,%7}, {%8,%9}, {%0,%1,%2,%3};"
                            : "+f"(acc[f][2 * jj][0]), "+f"(acc[f][2 * jj][1]),
                              "+f"(acc[f][2 * jj][2]), "+f"(acc[f][2 * jj][3])
                            : "r"(a[f][0]), "r"(a[f][1]), "r"(a[f][2]), "r"(a[f][3]),
                              "r"(bq[jj][0]), "r"(bq[jj][1]));
                        asm volatile(
                            "mma.sync.aligned.m16n8k16.row.col.f32.f16.f16.f32 "
                            "{%0,%1,%2,%3}, {%4,%5,%6,%7}, {%8,%9}, {%0,%1,%2,%3};"
                            : "+f"(acc[f][2 * jj + 1][0]), "+f"(acc[f][2 * jj + 1][1]),
                              "+f"(acc[f][2 * jj + 1][2]), "+f"(acc[f][2 * jj + 1][3])
                            : "r"(a[f][0]), "r"(a[f][1]), "r"(a[f][2]), "r"(a[f][3]),
                              "r"(bq[jj][2]), "r"(bq[jj][3]));
                    }
            }
        }
    }

    // epilogue: warp covers 64 m x 32 n of the 128x256 tile
#pragma unroll
    for (int f = 0; f < 4; ++f) {
        int co = mb + 16 * f + qid;
        float* o0 = out + ((size_t)(b * CO + co)) * HW + (nt << 8) + nb + 2 * tig;
        float* o1 = o0 + 8 * HW;
#pragma unroll
        for (int j = 0; j < 4; ++j) {
            *(float2*)(o0 + 8 * j) = make_float2(acc[f][j][0], acc[f][j][1]);
            *(float2*)(o1 + 8 * j) = make_float2(acc[f][j][2], acc[f][j][3]);
        }
    }
}

extern "C" void kernel_launch(void* const* d_in, const int* in_sizes, int n_in,
                              void* d_out, int out_size) {
    const float* feat = (const float*)d_in[0];   // (16,128,64,64)
    const float* wker = (const float*)d_in[1];   // (16,128,128,3,3)
    float* out = (float*)d_out;

    cudaFuncSetAttribute(conv_kernel, cudaFuncAttributeMaxDynamicSharedMemorySize, SMEM_BYTES);

    prep_w<<<dim3(64, BB), 256>>>(wker);
    conv_kernel<<<dim3(16, BB), 512, SMEM_BYTES>>>(feat, out);
}